// round 4
// baseline (speedup 1.0000x reference)
#include <cuda_runtime.h>
#include <math.h>
#include <stdint.h>

// ---------------------------------------------------------------------------
// GatedDeltaNet forward, fp32 baseline.
// B=2, S=4096, H=1024, NKH=8, NVH=16, DK=DV=64, CONV_DIM=2048, KSZ=4
// ---------------------------------------------------------------------------

#define BB        2
#define SSEQ      4096
#define HH        1024
#define NKH_      8
#define NVH_      16
#define DK_       64
#define DV_       64
#define KEY_DIM_  512           // NKH*DK
#define VAL_DIM_  1024          // NVH*DV
#define CONV_DIM_ 2048          // 2*KEY_DIM + VAL_DIM
#define NTOK      (BB*SSEQ)     // 8192

// Scratch (device globals; no dynamic allocation allowed)
__device__ float g_mixed[(size_t)NTOK * CONV_DIM_];   // pre-conv qkv
__device__ float g_conv [(size_t)NTOK * CONV_DIM_];   // post conv+silu
__device__ float g_zs   [(size_t)NTOK * VAL_DIM_];    // silu(z)
__device__ float g_o    [(size_t)NTOK * VAL_DIM_];    // recurrence output
__device__ float g_h    [(size_t)NTOK * VAL_DIM_];    // post gated-rmsnorm
__device__ float g_decay[(size_t)NTOK * NVH_];        // exp(g_t)
__device__ float g_beta [(size_t)NTOK * NVH_];        // sigmoid

// ---------------------------------------------------------------------------
// Generic fp32 GEMM:  C[m,n] = act( sum_k A[m,k] * B[n,k] )   ("NT" layout)
// BM=BN=128, BK=8, 256 threads, 8x8 per-thread tile, double-buffered smem.
// Requires M%128==0, N%128==0, K%8==0 (true for all uses here).
// ACT: 0 = none, 1 = silu
// ---------------------------------------------------------------------------
template<int ACT>
__global__ void __launch_bounds__(256) sgemm_nt(const float* __restrict__ A,
                                                const float* __restrict__ B,
                                                float* __restrict__ C,
                                                int M, int N, int K)
{
    constexpr int BM = 128, BN = 128, BK = 8;
    __shared__ __align__(16) float As[2][BK][BM];
    __shared__ __align__(16) float Bs[2][BK][BN];

    const int bm  = blockIdx.y * BM;
    const int bn  = blockIdx.x * BN;
    const int tid = threadIdx.x;

    const int lrow = tid >> 1;          // 0..127
    const int lcol = (tid & 1) << 2;    // 0 or 4
    const float* Ap = A + (size_t)(bm + lrow) * K + lcol;
    const float* Bp = B + (size_t)(bn + lrow) * K + lcol;

    const int tx = tid & 15;            // 0..15 -> N
    const int ty = tid >> 4;            // 0..15 -> M

    float acc[8][8];
#pragma unroll
    for (int i = 0; i < 8; i++)
#pragma unroll
        for (int j = 0; j < 8; j++) acc[i][j] = 0.f;

    // first tile load
    {
        float4 av = *(const float4*)Ap;
        float4 bv = *(const float4*)Bp;
        As[0][lcol + 0][lrow] = av.x; As[0][lcol + 1][lrow] = av.y;
        As[0][lcol + 2][lrow] = av.z; As[0][lcol + 3][lrow] = av.w;
        Bs[0][lcol + 0][lrow] = bv.x; Bs[0][lcol + 1][lrow] = bv.y;
        Bs[0][lcol + 2][lrow] = bv.z; Bs[0][lcol + 3][lrow] = bv.w;
    }
    __syncthreads();

    int buf = 0;
    for (int k0 = BK; k0 <= K; k0 += BK) {
        float4 avn, bvn;
        const bool more = (k0 < K);
        if (more) {
            avn = *(const float4*)(Ap + k0);
            bvn = *(const float4*)(Bp + k0);
        }
#pragma unroll
        for (int kk = 0; kk < BK; kk++) {
            float a[8], b[8];
            *(float4*)&a[0] = *(const float4*)&As[buf][kk][ty * 8];
            *(float4*)&a[4] = *(const float4*)&As[buf][kk][ty * 8 + 4];
            *(float4*)&b[0] = *(const float4*)&Bs[buf][kk][tx * 8];
            *(float4*)&b[4] = *(const float4*)&Bs[buf][kk][tx * 8 + 4];
#pragma unroll
            for (int i = 0; i < 8; i++)
#pragma unroll
                for (int j = 0; j < 8; j++)
                    acc[i][j] = fmaf(a[i], b[j], acc[i][j]);
        }
        if (more) {
            buf ^= 1;
            As[buf][lcol + 0][lrow] = avn.x; As[buf][lcol + 1][lrow] = avn.y;
            As[buf][lcol + 2][lrow] = avn.z; As[buf][lcol + 3][lrow] = avn.w;
            Bs[buf][lcol + 0][lrow] = bvn.x; Bs[buf][lcol + 1][lrow] = bvn.y;
            Bs[buf][lcol + 2][lrow] = bvn.z; Bs[buf][lcol + 3][lrow] = bvn.w;
            __syncthreads();
        }
    }

    // epilogue
#pragma unroll
    for (int i = 0; i < 8; i++) {
        float* crow = C + (size_t)(bm + ty * 8 + i) * N + (bn + tx * 8);
        float v[8];
#pragma unroll
        for (int j = 0; j < 8; j++) {
            float x = acc[i][j];
            if (ACT == 1) x = x * (1.f / (1.f + __expf(-x)));   // silu
            v[j] = x;
        }
        *(float4*)(crow)     = make_float4(v[0], v[1], v[2], v[3]);
        *(float4*)(crow + 4) = make_float4(v[4], v[5], v[6], v[7]);
    }
}

// ---------------------------------------------------------------------------
// beta / decay projection: out j<16 -> beta_j, j>=16 -> decay (exp(g)) for head j-16
// one thread per (token, j), K=1024 dot with float4 loads.
// ---------------------------------------------------------------------------
__global__ void __launch_bounds__(256) proj_gba(const float* __restrict__ hidden,
                                                const float* __restrict__ Wb,
                                                const float* __restrict__ Wa,
                                                const float* __restrict__ dt_bias,
                                                const float* __restrict__ A_log)
{
    int idx = blockIdx.x * blockDim.x + threadIdx.x;
    if (idx >= NTOK * 32) return;
    const int token = idx >> 5;
    const int j     = idx & 31;
    const float* hrow = hidden + (size_t)token * HH;
    const float* w    = (j < 16) ? (Wb + (size_t)j * HH) : (Wa + (size_t)(j - 16) * HH);

    float a0 = 0.f, a1 = 0.f, a2 = 0.f, a3 = 0.f;
#pragma unroll 8
    for (int k = 0; k < HH; k += 4) {
        float4 hv = *(const float4*)(hrow + k);
        float4 wv = *(const float4*)(w + k);
        a0 = fmaf(hv.x, wv.x, a0);
        a1 = fmaf(hv.y, wv.y, a1);
        a2 = fmaf(hv.z, wv.z, a2);
        a3 = fmaf(hv.w, wv.w, a3);
    }
    float acc = (a0 + a1) + (a2 + a3);
    if (j < 16) {
        g_beta[(size_t)token * NVH_ + j] = 1.f / (1.f + expf(-acc));
    } else {
        const int h = j - 16;
        float x  = acc + dt_bias[h];
        float sp = (x > 20.f) ? x : log1pf(expf(x));        // softplus
        float g  = -expf(A_log[h]) * sp;
        g_decay[(size_t)token * NVH_ + h] = expf(g);
    }
}

// ---------------------------------------------------------------------------
// depthwise causal conv (k=4) + silu.  One thread per (token, 4 channels).
// y[t] = w0*x[t-3] + w1*x[t-2] + w2*x[t-1] + w3*x[t]   (zero pad per batch)
// ---------------------------------------------------------------------------
__global__ void __launch_bounds__(256) conv_silu_kernel(const float* __restrict__ conv_w)
{
    int idx = blockIdx.x * blockDim.x + threadIdx.x;
    if (idx >= NTOK * (CONV_DIM_ / 4)) return;
    const int ch4   = idx & (CONV_DIM_ / 4 - 1);   // 0..511
    const int token = idx >> 9;
    const int t     = token & (SSEQ - 1);
    const int ch    = ch4 * 4;

    const float* w = conv_w + (size_t)ch * 4;      // [ch][1][4] taps contiguous
    float4 w0 = *(const float4*)(w);
    float4 w1 = *(const float4*)(w + 4);
    float4 w2 = *(const float4*)(w + 8);
    float4 w3 = *(const float4*)(w + 12);

    const float* xc = g_mixed + (size_t)token * CONV_DIM_ + ch;
    const float4 zero = make_float4(0.f, 0.f, 0.f, 0.f);
    float4 x0  = *(const float4*)xc;
    float4 xm1 = (t >= 1) ? *(const float4*)(xc - 1 * CONV_DIM_) : zero;
    float4 xm2 = (t >= 2) ? *(const float4*)(xc - 2 * CONV_DIM_) : zero;
    float4 xm3 = (t >= 3) ? *(const float4*)(xc - 3 * CONV_DIM_) : zero;

    float y0 = fmaf(w0.x, xm3.x, fmaf(w0.y, xm2.x, fmaf(w0.z, xm1.x, w0.w * x0.x)));
    float y1 = fmaf(w1.x, xm3.y, fmaf(w1.y, xm2.y, fmaf(w1.z, xm1.y, w1.w * x0.y)));
    float y2 = fmaf(w2.x, xm3.z, fmaf(w2.y, xm2.z, fmaf(w2.z, xm1.z, w2.w * x0.z)));
    float y3 = fmaf(w3.x, xm3.w, fmaf(w3.y, xm2.w, fmaf(w3.z, xm1.w, w3.w * x0.w)));

    float4 r;
    r.x = y0 * (1.f / (1.f + __expf(-y0)));
    r.y = y1 * (1.f / (1.f + __expf(-y1)));
    r.z = y2 * (1.f / (1.f + __expf(-y2)));
    r.w = y3 * (1.f / (1.f + __expf(-y3)));
    *(float4*)(g_conv + (size_t)token * CONV_DIM_ + ch) = r;
}

// ---------------------------------------------------------------------------
// Gated delta-rule recurrence. Column-parallel: each v-column of the state
// evolves independently. Warp handles 4 columns: 8 lanes/col x 8 rows/lane.
// Grid = B*NVH*8 CTAs of 64 threads (2 warps -> 8 cols per CTA) to spread
// the 512 independent warps across more SMs.
// Distance-2 register prefetch of per-step inputs.
// ---------------------------------------------------------------------------
__device__ __forceinline__ void rec_load(int t,
        const float* __restrict__ kb, const float* __restrict__ qb,
        const float* __restrict__ vb, const float* __restrict__ db,
        const float* __restrict__ bbp,
        float* kk, float* qq, float& vv, float& dd, float& bt)
{
    const size_t off = (size_t)t * CONV_DIM_;
    float4 a  = *(const float4*)(kb + off);
    float4 a2 = *(const float4*)(kb + off + 4);
    kk[0] = a.x;  kk[1] = a.y;  kk[2] = a.z;  kk[3] = a.w;
    kk[4] = a2.x; kk[5] = a2.y; kk[6] = a2.z; kk[7] = a2.w;
    float4 c  = *(const float4*)(qb + off);
    float4 c2 = *(const float4*)(qb + off + 4);
    qq[0] = c.x;  qq[1] = c.y;  qq[2] = c.z;  qq[3] = c.w;
    qq[4] = c2.x; qq[5] = c2.y; qq[6] = c2.z; qq[7] = c2.w;
    vv = vb[off];
    dd = db[(size_t)t * NVH_];
    bt = bbp[(size_t)t * NVH_];
}

__global__ void __launch_bounds__(64) recurrence_kernel()
{
    const int bh     = blockIdx.x >> 3;      // 0..31  (b*16+h)
    const int colblk = blockIdx.x & 7;       // 0..7
    const int b  = bh >> 4;
    const int h  = bh & 15;
    const int kh = h >> 1;                   // GQA: rep=2
    const int warp = threadIdx.x >> 5;       // 0..1
    const int lane = threadIdx.x & 31;
    const int cg = lane >> 3;                // column within warp (0..3)
    const int rg = lane & 7;                 // row group (0..7)
    const int c  = colblk * 8 + warp * 4 + cg;
    const int r0 = rg * 8;

    const float* base = g_conv + (size_t)b * SSEQ * CONV_DIM_;
    const float* qb = base + kh * DK_ + r0;
    const float* kb = base + KEY_DIM_ + kh * DK_ + r0;
    const float* vb = base + 2 * KEY_DIM_ + h * DV_ + c;
    const float* db = g_decay + (size_t)b * SSEQ * NVH_ + h;
    const float* bbp = g_beta + (size_t)b * SSEQ * NVH_ + h;
    float* ob = g_o + (size_t)b * SSEQ * VAL_DIM_ + h * DV_ + c;

    float S[8];
#pragma unroll
    for (int i = 0; i < 8; i++) S[i] = 0.f;

    float kA[8], qA[8], vA, dA, bA;
    float kB[8], qB[8], vB, dB, bBv;
    rec_load(0, kb, qb, vb, db, bbp, kA, qA, vA, dA, bA);
    rec_load(1, kb, qb, vb, db, bbp, kB, qB, vB, dB, bBv);

    const float qscale = 0.125f;   // DK^-0.5

#pragma unroll 2
    for (int t = 0; t < SSEQ; t++) {
        float kk[8], qq[8], vv, dd, bt;
        if ((t & 1) == 0) {
#pragma unroll
            for (int i = 0; i < 8; i++) { kk[i] = kA[i]; qq[i] = qA[i]; }
            vv = vA; dd = dA; bt = bA;
            if (t + 2 < SSEQ) rec_load(t + 2, kb, qb, vb, db, bbp, kA, qA, vA, dA, bA);
        } else {
#pragma unroll
            for (int i = 0; i < 8; i++) { kk[i] = kB[i]; qq[i] = qB[i]; }
            vv = vB; dd = dB; bt = bBv;
            if (t + 2 < SSEQ) rec_load(t + 2, kb, qb, vb, db, bbp, kB, qB, vB, dB, bBv);
        }

        // kv[c] = decay * <S_old[:,c], k>
        float kva = 0.f, kvb = 0.f;
#pragma unroll
        for (int i = 0; i < 8; i += 2) {
            kva = fmaf(kk[i],     S[i],     kva);
            kvb = fmaf(kk[i + 1], S[i + 1], kvb);
        }
        float kv = kva + kvb;
        kv += __shfl_xor_sync(0xffffffffu, kv, 4);
        kv += __shfl_xor_sync(0xffffffffu, kv, 2);
        kv += __shfl_xor_sync(0xffffffffu, kv, 1);
        kv *= dd;

        const float delta = (vv - kv) * bt;

        // S = decay*S + k*delta ;  o = <S_new, q>
        float oa = 0.f, obp = 0.f;
#pragma unroll
        for (int i = 0; i < 8; i++)
            S[i] = fmaf(dd, S[i], kk[i] * delta);
#pragma unroll
        for (int i = 0; i < 8; i += 2) {
            oa  = fmaf(qq[i],     S[i],     oa);
            obp = fmaf(qq[i + 1], S[i + 1], obp);
        }
        float ov = oa + obp;
        ov += __shfl_xor_sync(0xffffffffu, ov, 4);
        ov += __shfl_xor_sync(0xffffffffu, ov, 2);
        ov += __shfl_xor_sync(0xffffffffu, ov, 1);

        if (rg == 0) ob[(size_t)t * VAL_DIM_] = ov * qscale;
    }
}

// ---------------------------------------------------------------------------
// gated RMSNorm over DV=64: h = o * silu(z); h *= rsqrt(mean(h^2)+eps) * w
// One CTA per token (512 threads = 16 warps, warp per head, 2 elems/lane).
// ---------------------------------------------------------------------------
__global__ void __launch_bounds__(512) gated_rmsnorm(const float* __restrict__ nw)
{
    const int token = blockIdx.x;
    const int wid  = threadIdx.x >> 5;
    const int lane = threadIdx.x & 31;
    const size_t base = (size_t)token * VAL_DIM_ + wid * DV_;

    float o0 = g_o[base + lane],        o1 = g_o[base + lane + 32];
    float z0 = g_zs[base + lane],       z1 = g_zs[base + lane + 32];
    float h0 = o0 * z0, h1 = o1 * z1;
    float ss = h0 * h0 + h1 * h1;
    ss += __shfl_xor_sync(0xffffffffu, ss, 16);
    ss += __shfl_xor_sync(0xffffffffu, ss, 8);
    ss += __shfl_xor_sync(0xffffffffu, ss, 4);
    ss += __shfl_xor_sync(0xffffffffu, ss, 2);
    ss += __shfl_xor_sync(0xffffffffu, ss, 1);
    const float sc = rsqrtf(ss * (1.f / 64.f) + 1e-6f);
    g_h[base + lane]      = h0 * sc * nw[lane];
    g_h[base + lane + 32] = h1 * sc * nw[lane + 32];
}

// ---------------------------------------------------------------------------
extern "C" void kernel_launch(void* const* d_in, const int* in_sizes, int n_in,
                              void* d_out, int out_size)
{
    const float* hidden   = (const float*)d_in[0];
    const float* W_qkv    = (const float*)d_in[1];
    const float* conv_w   = (const float*)d_in[2];
    const float* W_z      = (const float*)d_in[3];
    const float* W_b      = (const float*)d_in[4];
    const float* W_a      = (const float*)d_in[5];
    const float* dt_bias  = (const float*)d_in[6];
    const float* A_log    = (const float*)d_in[7];
    const float* norm_w   = (const float*)d_in[8];
    const float* W_out    = (const float*)d_in[9];
    float* out = (float*)d_out;

    void *p_mixed, *p_zs, *p_h;
    cudaGetSymbolAddress(&p_mixed, g_mixed);
    cudaGetSymbolAddress(&p_zs,    g_zs);
    cudaGetSymbolAddress(&p_h,     g_h);

    // 1) QKV projection: [8192,1024] x [2048,1024]^T -> g_mixed
    sgemm_nt<0><<<dim3(CONV_DIM_ / 128, NTOK / 128), 256>>>(
        hidden, W_qkv, (float*)p_mixed, NTOK, CONV_DIM_, HH);

    // 2) Z projection + silu: -> g_zs
    sgemm_nt<1><<<dim3(VAL_DIM_ / 128, NTOK / 128), 256>>>(
        hidden, W_z, (float*)p_zs, NTOK, VAL_DIM_, HH);

    // 3) beta / decay
    proj_gba<<<(NTOK * 32 + 255) / 256, 256>>>(hidden, W_b, W_a, dt_bias, A_log);

    // 4) depthwise causal conv + silu: g_mixed -> g_conv
    conv_silu_kernel<<<(NTOK * (CONV_DIM_ / 4) + 255) / 256, 256>>>(conv_w);

    // 5) gated delta-rule recurrence: -> g_o
    recurrence_kernel<<<BB * NVH_ * 8, 64>>>();

    // 6) gated RMSNorm: -> g_h
    gated_rmsnorm<<<NTOK, 512>>>(norm_w);

    // 7) output projection: [8192,1024] x [1024,1024]^T -> d_out
    sgemm_nt<0><<<dim3(HH / 128, NTOK / 128), 256>>>(
        (const float*)p_h, W_out, out, NTOK, HH, VAL_DIM_);
}

// round 6
// speedup vs baseline: 1.1026x; 1.1026x over previous
#include <cuda_runtime.h>
#include <math.h>
#include <stdint.h>

// ---------------------------------------------------------------------------
// GatedDeltaNet forward.  GEMMs on tensor cores via 3xTF32 mma.sync
// (error-compensated -> fp32-grade accuracy), recurrence/conv/norm fp32 SIMT.
// B=2, S=4096, H=1024, NKH=8, NVH=16, DK=DV=64, CONV_DIM=2048, KSZ=4
// ---------------------------------------------------------------------------

#define BB        2
#define SSEQ      4096
#define HH        1024
#define NKH_      8
#define NVH_      16
#define DK_       64
#define DV_       64
#define KEY_DIM_  512           // NKH*DK
#define VAL_DIM_  1024          // NVH*DV
#define CONV_DIM_ 2048          // 2*KEY_DIM + VAL_DIM
#define NTOK      (BB*SSEQ)     // 8192

// Scratch (device globals; no dynamic allocation allowed)
__device__ float g_mixed[(size_t)NTOK * CONV_DIM_];   // pre-conv qkv
__device__ float g_conv [(size_t)NTOK * CONV_DIM_];   // post conv+silu
__device__ float g_zs   [(size_t)NTOK * VAL_DIM_];    // silu(z)
__device__ float g_o    [(size_t)NTOK * VAL_DIM_];    // recurrence output
__device__ float g_h    [(size_t)NTOK * VAL_DIM_];    // post gated-rmsnorm
__device__ float g_decay[(size_t)NTOK * NVH_];        // exp(g_t)
__device__ float g_beta [(size_t)NTOK * NVH_];        // sigmoid

// ---------------------------------------------------------------------------
// tf32 helpers
// ---------------------------------------------------------------------------
__device__ __forceinline__ uint32_t f2tf32(float x) {
    uint32_t r;
    asm("cvt.rna.tf32.f32 %0, %1;" : "=r"(r) : "f"(x));
    return r;
}
__device__ __forceinline__ void split_tf32(float x, uint32_t& hi, uint32_t& lo) {
    hi = f2tf32(x);
    float rem = x - __uint_as_float(hi);   // exact in fp32
    lo = f2tf32(rem);
}
__device__ __forceinline__ void mma_tf32(float* c,
        uint32_t a0, uint32_t a1, uint32_t a2, uint32_t a3,
        uint32_t b0, uint32_t b1) {
    asm("mma.sync.aligned.m16n8k8.row.col.f32.tf32.tf32.f32 "
        "{%0,%1,%2,%3}, {%4,%5,%6,%7}, {%8,%9}, {%0,%1,%2,%3};"
        : "+f"(c[0]), "+f"(c[1]), "+f"(c[2]), "+f"(c[3])
        : "r"(a0), "r"(a1), "r"(a2), "r"(a3), "r"(b0), "r"(b1));
}

// ---------------------------------------------------------------------------
// Tensor-core GEMM: C[m,n] = act( sum_k A[m,k] * B[n,k] )  ("NT" layout)
// 128x128x16 CTA tile, 8 warps, 64x32 warp tile (4x4 m16n8k8 tiles),
// 3xTF32 compensation (hi*hi + hi*lo + lo*hi) -> ~2^-24 residual.
// Requires M%128==0, N%128==0, K%16==0.
// ACT: 0 = none, 1 = silu
// ---------------------------------------------------------------------------
template<int ACT>
__global__ void __launch_bounds__(256) mma_gemm_nt(const float* __restrict__ A,
                                                   const float* __restrict__ B,
                                                   float* __restrict__ C,
                                                   int M, int N, int K)
{
    constexpr int BM = 128, BN = 128, BK = 16, LDSM = 20; // stride 20: conflict-free + 16B-aligned
    __shared__ __align__(16) float As[2][BM][LDSM];
    __shared__ __align__(16) float Bs[2][BN][LDSM];

    const int bm  = blockIdx.y * BM;
    const int bn  = blockIdx.x * BN;
    const int tid = threadIdx.x;
    const int wid  = tid >> 5;
    const int lane = tid & 31;
    const int gid  = lane >> 2;          // 0..7
    const int tig  = lane & 3;           // 0..3
    const int warpM = (wid >> 2) * 64;   // 0 or 64
    const int warpN = (wid & 3) * 32;    // 0,32,64,96

    // global->smem mapping: 2 float4 per thread per matrix
    const int lrow = tid >> 1;           // 0..127
    const int lcol = (tid & 1) * 8;      // 0 or 8
    const float* Ap = A + (size_t)(bm + lrow) * K + lcol;
    const float* Bp = B + (size_t)(bn + lrow) * K + lcol;

    float acc[4][4][4];                  // [mt][nt][frag]
#pragma unroll
    for (int i = 0; i < 4; i++)
#pragma unroll
        for (int j = 0; j < 4; j++)
#pragma unroll
            for (int r = 0; r < 4; r++) acc[i][j][r] = 0.f;

    // first tile
    {
        float4 a0 = *(const float4*)(Ap);
        float4 a1 = *(const float4*)(Ap + 4);
        float4 b0 = *(const float4*)(Bp);
        float4 b1 = *(const float4*)(Bp + 4);
        *(float4*)&As[0][lrow][lcol]     = a0;
        *(float4*)&As[0][lrow][lcol + 4] = a1;
        *(float4*)&Bs[0][lrow][lcol]     = b0;
        *(float4*)&Bs[0][lrow][lcol + 4] = b1;
    }
    __syncthreads();

    int buf = 0;
    for (int k0 = BK; k0 <= K; k0 += BK) {
        float4 an0, an1, bn0, bn1;
        const bool more = (k0 < K);
        if (more) {
            an0 = *(const float4*)(Ap + k0);
            an1 = *(const float4*)(Ap + k0 + 4);
            bn0 = *(const float4*)(Bp + k0);
            bn1 = *(const float4*)(Bp + k0 + 4);
        }

#pragma unroll
        for (int ks = 0; ks < 2; ks++) {
            const int kb = ks * 8;
            // A fragments (4 m-tiles), split hi/lo
            uint32_t ah[4][4], al[4][4];
#pragma unroll
            for (int mt = 0; mt < 4; mt++) {
                const int mrow = warpM + mt * 16 + gid;
                float x0 = As[buf][mrow][kb + tig];
                float x1 = As[buf][mrow + 8][kb + tig];
                float x2 = As[buf][mrow][kb + tig + 4];
                float x3 = As[buf][mrow + 8][kb + tig + 4];
                split_tf32(x0, ah[mt][0], al[mt][0]);
                split_tf32(x1, ah[mt][1], al[mt][1]);
                split_tf32(x2, ah[mt][2], al[mt][2]);
                split_tf32(x3, ah[mt][3], al[mt][3]);
            }
            // B fragments (4 n-tiles), split hi/lo
            uint32_t bh[4][2], bl[4][2];
#pragma unroll
            for (int nt = 0; nt < 4; nt++) {
                const int nrow = warpN + nt * 8 + gid;
                float y0 = Bs[buf][nrow][kb + tig];
                float y1 = Bs[buf][nrow][kb + tig + 4];
                split_tf32(y0, bh[nt][0], bl[nt][0]);
                split_tf32(y1, bh[nt][1], bl[nt][1]);
            }
            // 3xTF32 mma
#pragma unroll
            for (int mt = 0; mt < 4; mt++)
#pragma unroll
                for (int nt = 0; nt < 4; nt++) {
                    mma_tf32(acc[mt][nt], ah[mt][0], ah[mt][1], ah[mt][2], ah[mt][3],
                             bh[nt][0], bh[nt][1]);
                    mma_tf32(acc[mt][nt], ah[mt][0], ah[mt][1], ah[mt][2], ah[mt][3],
                             bl[nt][0], bl[nt][1]);
                    mma_tf32(acc[mt][nt], al[mt][0], al[mt][1], al[mt][2], al[mt][3],
                             bh[nt][0], bh[nt][1]);
                }
        }

        if (more) {
            buf ^= 1;
            *(float4*)&As[buf][lrow][lcol]     = an0;
            *(float4*)&As[buf][lrow][lcol + 4] = an1;
            *(float4*)&Bs[buf][lrow][lcol]     = bn0;
            *(float4*)&Bs[buf][lrow][lcol + 4] = bn1;
            __syncthreads();
        }
    }

    // epilogue: c0/c1 at (row, 2tig), c2/c3 at (row+8, 2tig)
#pragma unroll
    for (int mt = 0; mt < 4; mt++) {
        const int r0 = bm + warpM + mt * 16 + gid;
#pragma unroll
        for (int nt = 0; nt < 4; nt++) {
            const int cc = bn + warpN + nt * 8 + 2 * tig;
            float v0 = acc[mt][nt][0], v1 = acc[mt][nt][1];
            float v2 = acc[mt][nt][2], v3 = acc[mt][nt][3];
            if (ACT == 1) {
                v0 = v0 * (1.f / (1.f + __expf(-v0)));
                v1 = v1 * (1.f / (1.f + __expf(-v1)));
                v2 = v2 * (1.f / (1.f + __expf(-v2)));
                v3 = v3 * (1.f / (1.f + __expf(-v3)));
            }
            *(float2*)(C + (size_t)r0 * N + cc)       = make_float2(v0, v1);
            *(float2*)(C + (size_t)(r0 + 8) * N + cc) = make_float2(v2, v3);
        }
    }
}

// ---------------------------------------------------------------------------
// beta / decay projection: out j<16 -> beta_j, j>=16 -> decay (exp(g)) for head j-16
// one thread per (token, j), K=1024 dot with float4 loads.
// ---------------------------------------------------------------------------
__global__ void __launch_bounds__(256) proj_gba(const float* __restrict__ hidden,
                                                const float* __restrict__ Wb,
                                                const float* __restrict__ Wa,
                                                const float* __restrict__ dt_bias,
                                                const float* __restrict__ A_log)
{
    int idx = blockIdx.x * blockDim.x + threadIdx.x;
    if (idx >= NTOK * 32) return;
    const int token = idx >> 5;
    const int j     = idx & 31;
    const float* hrow = hidden + (size_t)token * HH;
    const float* w    = (j < 16) ? (Wb + (size_t)j * HH) : (Wa + (size_t)(j - 16) * HH);

    float a0 = 0.f, a1 = 0.f, a2 = 0.f, a3 = 0.f;
#pragma unroll 8
    for (int k = 0; k < HH; k += 4) {
        float4 hv = *(const float4*)(hrow + k);
        float4 wv = *(const float4*)(w + k);
        a0 = fmaf(hv.x, wv.x, a0);
        a1 = fmaf(hv.y, wv.y, a1);
        a2 = fmaf(hv.z, wv.z, a2);
        a3 = fmaf(hv.w, wv.w, a3);
    }
    float acc = (a0 + a1) + (a2 + a3);
    if (j < 16) {
        g_beta[(size_t)token * NVH_ + j] = 1.f / (1.f + expf(-acc));
    } else {
        const int h = j - 16;
        float x  = acc + dt_bias[h];
        float sp = (x > 20.f) ? x : log1pf(expf(x));        // softplus
        float g  = -expf(A_log[h]) * sp;
        g_decay[(size_t)token * NVH_ + h] = expf(g);
    }
}

// ---------------------------------------------------------------------------
// depthwise causal conv (k=4) + silu.  One thread per (token, 4 channels).
// y[t] = w0*x[t-3] + w1*x[t-2] + w2*x[t-1] + w3*x[t]   (zero pad per batch)
// ---------------------------------------------------------------------------
__global__ void __launch_bounds__(256) conv_silu_kernel(const float* __restrict__ conv_w)
{
    int idx = blockIdx.x * blockDim.x + threadIdx.x;
    if (idx >= NTOK * (CONV_DIM_ / 4)) return;
    const int ch4   = idx & (CONV_DIM_ / 4 - 1);   // 0..511
    const int token = idx >> 9;
    const int t     = token & (SSEQ - 1);
    const int ch    = ch4 * 4;

    const float* w = conv_w + (size_t)ch * 4;      // [ch][1][4] taps contiguous
    float4 w0 = *(const float4*)(w);
    float4 w1 = *(const float4*)(w + 4);
    float4 w2 = *(const float4*)(w + 8);
    float4 w3 = *(const float4*)(w + 12);

    const float* xc = g_mixed + (size_t)token * CONV_DIM_ + ch;
    const float4 zero = make_float4(0.f, 0.f, 0.f, 0.f);
    float4 x0  = *(const float4*)xc;
    float4 xm1 = (t >= 1) ? *(const float4*)(xc - 1 * CONV_DIM_) : zero;
    float4 xm2 = (t >= 2) ? *(const float4*)(xc - 2 * CONV_DIM_) : zero;
    float4 xm3 = (t >= 3) ? *(const float4*)(xc - 3 * CONV_DIM_) : zero;

    float y0 = fmaf(w0.x, xm3.x, fmaf(w0.y, xm2.x, fmaf(w0.z, xm1.x, w0.w * x0.x)));
    float y1 = fmaf(w1.x, xm3.y, fmaf(w1.y, xm2.y, fmaf(w1.z, xm1.y, w1.w * x0.y)));
    float y2 = fmaf(w2.x, xm3.z, fmaf(w2.y, xm2.z, fmaf(w2.z, xm1.z, w2.w * x0.z)));
    float y3 = fmaf(w3.x, xm3.w, fmaf(w3.y, xm2.w, fmaf(w3.z, xm1.w, w3.w * x0.w)));

    float4 r;
    r.x = y0 * (1.f / (1.f + __expf(-y0)));
    r.y = y1 * (1.f / (1.f + __expf(-y1)));
    r.z = y2 * (1.f / (1.f + __expf(-y2)));
    r.w = y3 * (1.f / (1.f + __expf(-y3)));
    *(float4*)(g_conv + (size_t)token * CONV_DIM_ + ch) = r;
}

// ---------------------------------------------------------------------------
// Gated delta-rule recurrence. Column-parallel: each v-column of the state
// evolves independently. Warp handles 4 columns: 8 lanes/col x 8 rows/lane.
// Grid = B*NVH*8 CTAs of 64 threads (2 warps -> 8 cols per CTA).
// Distance-2 register prefetch of per-step inputs.
// ---------------------------------------------------------------------------
__device__ __forceinline__ void rec_load(int t,
        const float* __restrict__ kb, const float* __restrict__ qb,
        const float* __restrict__ vb, const float* __restrict__ db,
        const float* __restrict__ bbp,
        float* kk, float* qq, float& vv, float& dd, float& bt)
{
    const size_t off = (size_t)t * CONV_DIM_;
    float4 a  = *(const float4*)(kb + off);
    float4 a2 = *(const float4*)(kb + off + 4);
    kk[0] = a.x;  kk[1] = a.y;  kk[2] = a.z;  kk[3] = a.w;
    kk[4] = a2.x; kk[5] = a2.y; kk[6] = a2.z; kk[7] = a2.w;
    float4 c  = *(const float4*)(qb + off);
    float4 c2 = *(const float4*)(qb + off + 4);
    qq[0] = c.x;  qq[1] = c.y;  qq[2] = c.z;  qq[3] = c.w;
    qq[4] = c2.x; qq[5] = c2.y; qq[6] = c2.z; qq[7] = c2.w;
    vv = vb[off];
    dd = db[(size_t)t * NVH_];
    bt = bbp[(size_t)t * NVH_];
}

__global__ void __launch_bounds__(64) recurrence_kernel()
{
    const int bh     = blockIdx.x >> 3;      // 0..31  (b*16+h)
    const int colblk = blockIdx.x & 7;       // 0..7
    const int b  = bh >> 4;
    const int h  = bh & 15;
    const int kh = h >> 1;                   // GQA: rep=2
    const int warp = threadIdx.x >> 5;       // 0..1
    const int lane = threadIdx.x & 31;
    const int cg = lane >> 3;                // column within warp (0..3)
    const int rg = lane & 7;                 // row group (0..7)
    const int c  = colblk * 8 + warp * 4 + cg;
    const int r0 = rg * 8;

    const float* base = g_conv + (size_t)b * SSEQ * CONV_DIM_;
    const float* qb = base + kh * DK_ + r0;
    const float* kb = base + KEY_DIM_ + kh * DK_ + r0;
    const float* vb = base + 2 * KEY_DIM_ + h * DV_ + c;
    const float* db = g_decay + (size_t)b * SSEQ * NVH_ + h;
    const float* bbp = g_beta + (size_t)b * SSEQ * NVH_ + h;
    float* ob = g_o + (size_t)b * SSEQ * VAL_DIM_ + h * DV_ + c;

    float S[8];
#pragma unroll
    for (int i = 0; i < 8; i++) S[i] = 0.f;

    float kA[8], qA[8], vA, dA, bA;
    float kB[8], qB[8], vB, dB, bBv;
    rec_load(0, kb, qb, vb, db, bbp, kA, qA, vA, dA, bA);
    rec_load(1, kb, qb, vb, db, bbp, kB, qB, vB, dB, bBv);

    const float qscale = 0.125f;   // DK^-0.5

#pragma unroll 2
    for (int t = 0; t < SSEQ; t++) {
        float kk[8], qq[8], vv, dd, bt;
        if ((t & 1) == 0) {
#pragma unroll
            for (int i = 0; i < 8; i++) { kk[i] = kA[i]; qq[i] = qA[i]; }
            vv = vA; dd = dA; bt = bA;
            if (t + 2 < SSEQ) rec_load(t + 2, kb, qb, vb, db, bbp, kA, qA, vA, dA, bA);
        } else {
#pragma unroll
            for (int i = 0; i < 8; i++) { kk[i] = kB[i]; qq[i] = qB[i]; }
            vv = vB; dd = dB; bt = bBv;
            if (t + 2 < SSEQ) rec_load(t + 2, kb, qb, vb, db, bbp, kB, qB, vB, dB, bBv);
        }

        // kv[c] = decay * <S_old[:,c], k>
        float kva = 0.f, kvb = 0.f;
#pragma unroll
        for (int i = 0; i < 8; i += 2) {
            kva = fmaf(kk[i],     S[i],     kva);
            kvb = fmaf(kk[i + 1], S[i + 1], kvb);
        }
        float kv = kva + kvb;
        kv += __shfl_xor_sync(0xffffffffu, kv, 4);
        kv += __shfl_xor_sync(0xffffffffu, kv, 2);
        kv += __shfl_xor_sync(0xffffffffu, kv, 1);
        kv *= dd;

        const float delta = (vv - kv) * bt;

        // S = decay*S + k*delta ;  o = <S_new, q>
        float oa = 0.f, obp = 0.f;
#pragma unroll
        for (int i = 0; i < 8; i++)
            S[i] = fmaf(dd, S[i], kk[i] * delta);
#pragma unroll
        for (int i = 0; i < 8; i += 2) {
            oa  = fmaf(qq[i],     S[i],     oa);
            obp = fmaf(qq[i + 1], S[i + 1], obp);
        }
        float ov = oa + obp;
        ov += __shfl_xor_sync(0xffffffffu, ov, 4);
        ov += __shfl_xor_sync(0xffffffffu, ov, 2);
        ov += __shfl_xor_sync(0xffffffffu, ov, 1);

        if (rg == 0) ob[(size_t)t * VAL_DIM_] = ov * qscale;
    }
}

// ---------------------------------------------------------------------------
// gated RMSNorm over DV=64: h = o * silu(z); h *= rsqrt(mean(h^2)+eps) * w
// One CTA per token (512 threads = 16 warps, warp per head, 2 elems/lane).
// ---------------------------------------------------------------------------
__global__ void __launch_bounds__(512) gated_rmsnorm(const float* __restrict__ nw)
{
    const int token = blockIdx.x;
    const int wid  = threadIdx.x >> 5;
    const int lane = threadIdx.x & 31;
    const size_t base = (size_t)token * VAL_DIM_ + wid * DV_;

    float o0 = g_o[base + lane],        o1 = g_o[base + lane + 32];
    float z0 = g_zs[base + lane],       z1 = g_zs[base + lane + 32];
    float h0 = o0 * z0, h1 = o1 * z1;
    float ss = h0 * h0 + h1 * h1;
    ss += __shfl_xor_sync(0xffffffffu, ss, 16);
    ss += __shfl_xor_sync(0xffffffffu, ss, 8);
    ss += __shfl_xor_sync(0xffffffffu, ss, 4);
    ss += __shfl_xor_sync(0xffffffffu, ss, 2);
    ss += __shfl_xor_sync(0xffffffffu, ss, 1);
    const float sc = rsqrtf(ss * (1.f / 64.f) + 1e-6f);
    g_h[base + lane]      = h0 * sc * nw[lane];
    g_h[base + lane + 32] = h1 * sc * nw[lane + 32];
}

// ---------------------------------------------------------------------------
extern "C" void kernel_launch(void* const* d_in, const int* in_sizes, int n_in,
                              void* d_out, int out_size)
{
    const float* hidden   = (const float*)d_in[0];
    const float* W_qkv    = (const float*)d_in[1];
    const float* conv_w   = (const float*)d_in[2];
    const float* W_z      = (const float*)d_in[3];
    const float* W_b      = (const float*)d_in[4];
    const float* W_a      = (const float*)d_in[5];
    const float* dt_bias  = (const float*)d_in[6];
    const float* A_log    = (const float*)d_in[7];
    const float* norm_w   = (const float*)d_in[8];
    const float* W_out    = (const float*)d_in[9];
    float* out = (float*)d_out;

    void *p_mixed, *p_zs, *p_h;
    cudaGetSymbolAddress(&p_mixed, g_mixed);
    cudaGetSymbolAddress(&p_zs,    g_zs);
    cudaGetSymbolAddress(&p_h,     g_h);

    // 1) QKV projection: [8192,1024] x [2048,1024]^T -> g_mixed
    mma_gemm_nt<0><<<dim3(CONV_DIM_ / 128, NTOK / 128), 256>>>(
        hidden, W_qkv, (float*)p_mixed, NTOK, CONV_DIM_, HH);

    // 2) Z projection + silu: -> g_zs
    mma_gemm_nt<1><<<dim3(VAL_DIM_ / 128, NTOK / 128), 256>>>(
        hidden, W_z, (float*)p_zs, NTOK, VAL_DIM_, HH);

    // 3) beta / decay
    proj_gba<<<(NTOK * 32 + 255) / 256, 256>>>(hidden, W_b, W_a, dt_bias, A_log);

    // 4) depthwise causal conv + silu: g_mixed -> g_conv
    conv_silu_kernel<<<(NTOK * (CONV_DIM_ / 4) + 255) / 256, 256>>>(conv_w);

    // 5) gated delta-rule recurrence: -> g_o
    recurrence_kernel<<<BB * NVH_ * 8, 64>>>();

    // 6) gated RMSNorm: -> g_h
    gated_rmsnorm<<<NTOK, 512>>>(norm_w);

    // 7) output projection: [8192,1024] x [1024,1024]^T -> d_out
    mma_gemm_nt<0><<<dim3(HH / 128, NTOK / 128), 256>>>(
        (const float*)p_h, W_out, out, NTOK, HH, VAL_DIM_);
}